// round 14
// baseline (speedup 1.0000x reference)
#include <cuda_runtime.h>
#include <cuda_bf16.h>

#define R2C 0.70710678118654752f

__device__ __forceinline__ float soft05(float x) {
    return copysignf(fmaxf(fabsf(x) - 0.05f, 0.0f), x);
}

// x[8] -> o[8] = {RE0,RE1,RE2,RE3,RE4,SI1,SI2,SI3}, unnormalized.
__device__ __forceinline__ void dft8_real(const float* x, float* o) {
    float s04 = x[0] + x[4], d04 = x[0] - x[4];
    float s26 = x[2] + x[6], d26 = x[2] - x[6];
    float s15 = x[1] + x[5], d15 = x[1] - x[5];
    float s37 = x[3] + x[7], d37 = x[3] - x[7];
    float t1 = s04 + s26, t2 = s15 + s37;
    o[0] = t1 + t2; o[4] = t1 - t2; o[2] = s04 - s26;
    float u = d15 - d37, v = d15 + d37;
    o[1] = fmaf(R2C, u, d04); o[3] = fmaf(-R2C, u, d04);
    o[5] = fmaf(R2C, v, d26);
    o[6] = s15 - s37;
    o[7] = fmaf(R2C, v, -d26);
}

// o[u] = cosDFT_u(q) only (for lines with zero sine part).
__device__ __forceinline__ void dft8_cos(const float* q, float* o) {
    float s04 = q[0] + q[4], d04 = q[0] - q[4];
    float s26 = q[2] + q[6];
    float s15 = q[1] + q[5], d15 = q[1] - q[5];
    float s37 = q[3] + q[7], d37 = q[3] - q[7];
    float t1 = s04 + s26, t2 = s15 + s37;
    o[0] = t1 + t2; o[4] = t1 - t2;
    o[2] = s04 - s26; o[6] = o[2];
    float uq = d15 - d37;
    o[1] = fmaf(R2C, uq, d04); o[3] = fmaf(-R2C, uq, d04);
    o[5] = o[3]; o[7] = o[1];
}

// Dual conjugate lines: CR = cosDFT(q), SW = sinDFT(w).
// oA[u] = CR[u] - SW[u] (line tau), oB[u] = CR[u] + SW[u] (line 8-tau).
__device__ __forceinline__ void dft8_dual(const float* q, const float* w,
                                          float* oA, float* oB) {
    float s04 = q[0] + q[4], d04 = q[0] - q[4];
    float s26 = q[2] + q[6];
    float s15 = q[1] + q[5], d15 = q[1] - q[5];
    float s37 = q[3] + q[7], d37 = q[3] - q[7];
    float t1 = s04 + s26, t2 = s15 + s37;
    float CR0 = t1 + t2, CR4 = t1 - t2, CR2 = s04 - s26;
    float uq = d15 - d37;
    float CR1 = fmaf(R2C, uq, d04), CR3 = fmaf(-R2C, uq, d04);
    float d26w = w[2] - w[6];
    float vw = (w[1] - w[5]) + (w[3] - w[7]);
    float SW1 = fmaf(R2C, vw, d26w);
    float SW2 = (w[1] + w[5]) - (w[3] + w[7]);
    float SW3 = fmaf(R2C, vw, -d26w);
    oA[0] = CR0;        oB[0] = CR0;
    oA[4] = CR4;        oB[4] = CR4;
    oA[1] = CR1 - SW1;  oB[1] = CR1 + SW1;
    oA[2] = CR2 - SW2;  oB[2] = CR2 + SW2;
    oA[3] = CR3 - SW3;  oB[3] = CR3 + SW3;
    oA[5] = CR3 + SW3;  oB[5] = CR3 - SW3;
    oA[6] = CR2 + SW2;  oB[6] = CR2 - SW2;
    oA[7] = CR1 + SW1;  oB[7] = CR1 - SW1;
}

// Haar refine for a row pair (fully thread-local).
__device__ __forceinline__ void haar_pair(const float* e, const float* o,
                                          float* re, float* ro) {
    #pragma unroll
    for (int m = 0; m < 4; m++) {
        float a = e[2*m], b = e[2*m+1], c = o[2*m], d = o[2*m+1];
        float u0 = a + b, v0 = a - b, u1 = c + d, v1 = c - d;
        float LL = (u0 + u1) * 0.5f;
        float LH = soft05((u0 - u1) * 0.5f);
        float HL = soft05((v0 + v1) * 0.5f);
        float HH = soft05((v0 - v1) * 0.5f);
        float p  = LL + LH, qd = HL + HH;
        float rr = LL - LH, sd = HL - HH;
        re[2*m]   = 0.5f * (p + qd);
        re[2*m+1] = 0.5f * (p - qd);
        ro[2*m]   = 0.5f * (rr + sd);
        ro[2*m+1] = 0.5f * (rr - sd);
    }
}

__device__ __forceinline__ void nonlin8(float* c) {
    #pragma unroll
    for (int i = 0; i < 8; i++) {
        float v = c[i] * 0.125f;                 // fold ortho 1/8
        float m = fminf(fabsf(v) * 0.4f, 1.0f);  // shrink below 2.5
        v *= m;
        c[i] = fminf(fmaxf(v, -10.0f), 10.0f);   // clip
    }
}

// Vertical 3-tap blur for two consecutive rows, half-split to bound liveness.
__device__ __forceinline__ void vblur2(const float4* __restrict__ hp,
                                       float w0, float w1,
                                       float* g0, float* g1) {
    #pragma unroll
    for (int h = 0; h < 2; h++) {
        float4 A = hp[h], B = hp[2 + h], C = hp[4 + h], D = hp[6 + h];
        g0[4*h+0] = fmaf(w1, A.x + C.x, w0 * B.x);
        g0[4*h+1] = fmaf(w1, A.y + C.y, w0 * B.y);
        g0[4*h+2] = fmaf(w1, A.z + C.z, w0 * B.z);
        g0[4*h+3] = fmaf(w1, A.w + C.w, w0 * B.w);
        g1[4*h+0] = fmaf(w1, B.x + D.x, w0 * C.x);
        g1[4*h+1] = fmaf(w1, B.y + D.y, w0 * C.y);
        g1[4*h+2] = fmaf(w1, B.z + D.z, w0 * C.z);
        g1[4*h+3] = fmaf(w1, B.w + D.w, w0 * C.w);
    }
}

// Butterfly exchange: lane pair (L: hi=0, H: hi=1) swaps H's A with L's B.
// Each value lands in the slot it was sent from on the receiving lane.
__device__ __forceinline__ void xstep(float& A, float& B, int hi, int mask) {
    float snd = hi ? A : B;
    float rcv = __shfl_xor_sync(0xffffffffu, snd, mask);
    A = hi ? rcv : A;
    B = hi ? B : rcv;
}

// 4x4 transpose of 4-float packets P0..P3 across the lane quad (xor 8, 16).
// hi1 = p&1, hi2 = p&2. After: Pj = original packet P[p] of quad-lane j.
__device__ __forceinline__ void quad_transpose(float* P0, float* P1,
                                               float* P2, float* P3,
                                               int hi1, int hi2) {
    #pragma unroll
    for (int i = 0; i < 4; i++) xstep(P0[i], P1[i], hi1, 8);
    #pragma unroll
    for (int i = 0; i < 4; i++) xstep(P2[i], P3[i], hi1, 8);
    #pragma unroll
    for (int i = 0; i < 4; i++) xstep(P0[i], P2[i], hi2, 16);
    #pragma unroll
    for (int i = 0; i < 4; i++) xstep(P1[i], P3[i], hi2, 16);
}

#define PSTR 276   // panel stride floats (34 rows x 8 + pad; 276 % 8 == 4)

// CTA = 64x32 px, 128 threads, smem 8.8KB (12 CTAs/SM).
// Warp w = block-row w. lane: b = lane&7 (bcol), p = lane>>3 (quad index).
// Forward: thread owns block rows 2p,2p+1; after quad shfl-transpose it owns
// coefficient columns {p, 8-p}; after second transpose rows {p, 8-p}; an
// 8-shfl rotation re-pairs rows for Haar. ONE __syncthreads total.
__global__ __launch_bounds__(128, 12) void sas_fusedC_kernel(
    const float* __restrict__ in, float* __restrict__ out)
{
    __shared__ __align__(16) float smemA[8 * PSTR];  // hblur panels

    const int t = threadIdx.x;
    const int tileX = blockIdx.x * 64;
    const int tileY = blockIdx.y * 32;
    const int z = blockIdx.z;
    const float* img = in + (size_t)z * (512 * 512);

    const float e1 = expf(-0.78125f);            // exp(-1/(2*0.8^2))
    const float w0 = 1.0f / (1.0f + 2.0f * e1);
    const float w1 = e1 * w0;

    // ---- Loader: horizontal blur, global -> smem panels (34 rows) ----
    for (int s = t; s < 544; s += 128) {         // 34 rows x 16 f4
        int row = s >> 4, f4c = s & 15;
        int gy = tileY + row - 1;
        gy = (gy < 0) ? -gy : ((gy > 511) ? 1022 - gy : gy);
        const float* rp = img + (size_t)gy * 512;
        int base = tileX + f4c * 4;
        float4 A = *(const float4*)(rp + base);
        float lv = __shfl_up_sync(0xffffffffu, A.w, 1);
        float rv = __shfl_down_sync(0xffffffffu, A.x, 1);
        if (f4c == 0)  lv = (base == 0)   ? A.y : rp[base - 1];
        if (f4c == 15) rv = (base == 508) ? A.z : rp[base + 4];
        float4 o;
        o.x = fmaf(w1, lv  + A.y, w0 * A.x);
        o.y = fmaf(w1, A.x + A.z, w0 * A.y);
        o.z = fmaf(w1, A.y + A.w, w0 * A.z);
        o.w = fmaf(w1, A.z + rv,  w0 * A.w);
        *(float4*)(smemA + (f4c >> 1) * PSTR + row * 8 + (f4c & 1) * 4) = o;
    }
    __syncthreads();                             // ONLY barrier

    const int w = t >> 5;                        // warp = block-row
    const int lane = t & 31;
    const int b = lane & 7;                      // bcol
    const int p = lane >> 3;                     // quad index 0..3
    const int hi1 = p & 1, hi2 = p & 2;
    const float* panel = smemA + b * PSTR;

    // ---- Vertical blur rows 2p,2p+1 + row DFT -> packets ----
    float P0[4], P1[4], P2[4], P3[4];
    {
        const float4* hp = (const float4*)(panel + (8 * w + 2 * p) * 8);
        float g0[8], g1[8];
        vblur2(hp, w0, w1, g0, g1);
        float ta[8], tb[8];
        dft8_real(g0, ta);
        dft8_real(g1, tb);
        #pragma unroll
        for (int s = 0; s < 4; s++) {
            float* P = (s == 0) ? P0 : (s == 1) ? P1 : (s == 2) ? P2 : P3;
            P[0] = ta[s]; P[1] = ta[s + 4]; P[2] = tb[s]; P[3] = tb[s + 4];
        }
    }

    // ---- Transpose 1: rows -> columns (slots p, p+4 of all 8 rows) ----
    quad_transpose(P0, P1, P2, P3, hi1, hi2);
    // Pj = {ta_j[p], ta_j[p+4], tb_j[p], tb_j[p+4]}  (rows 2j, 2j+1)

    // ---- Forward column dual -> nonlin -> column DFT ----
    float sA[8], sB[8];
    {
        float q[8], ww[8];
        q[0] = P0[0]; ww[0] = P0[1]; q[1] = P0[2]; ww[1] = P0[3];
        q[2] = P1[0]; ww[2] = P1[1]; q[3] = P1[2]; ww[3] = P1[3];
        q[4] = P2[0]; ww[4] = P2[1]; q[5] = P2[2]; ww[5] = P2[3];
        q[6] = P3[0]; ww[6] = P3[1]; q[7] = P3[2]; ww[7] = P3[3];
        float cA[8], cB[8];
        if (p == 0) {                            // cols 0 and 4 (cos-only)
            dft8_cos(q, cA);
            dft8_cos(ww, cB);
        } else {                                 // cols p and 8-p
            dft8_dual(q, ww, cA, cB);
        }
        nonlin8(cA);
        nonlin8(cB);
        dft8_real(cA, sA);                       // compressed col p
        dft8_real(cB, sB);                       // compressed col (8-p)&7->4
    }

    // ---- Transpose 2: columns -> rows (slots p, p+4 of all 8 columns) ----
    #pragma unroll
    for (int s = 0; s < 4; s++) {
        float* P = (s == 0) ? P0 : (s == 1) ? P1 : (s == 2) ? P2 : P3;
        P[0] = sA[s]; P[1] = sA[s + 4]; P[2] = sB[s]; P[3] = sB[s + 4];
    }
    quad_transpose(P0, P1, P2, P3, hi1, hi2);
    // Pj = {colj[p], colj[p+4], colj2[p], colj2[p+4]}, colj2 = j?8-j:4

    // ---- Inverse row dual: rows p and 8-p (p=0: rows 0 and 4) ----
    float idA[8], idB[8];
    {
        float q[8], ww[8];
        q[0] = P0[0]; ww[0] = P0[1];             // col 0
        q[4] = P0[2]; ww[4] = P0[3];             // col 4
        q[1] = P1[0]; ww[1] = P1[1];             // col 1
        q[7] = P1[2]; ww[7] = P1[3];             // col 7
        q[2] = P2[0]; ww[2] = P2[1];             // col 2
        q[6] = P2[2]; ww[6] = P2[3];             // col 6
        q[3] = P3[0]; ww[3] = P3[1];             // col 3
        q[5] = P3[2]; ww[5] = P3[3];             // col 5
        if (p == 0) {
            dft8_cos(q, idA);                    // row 0
            dft8_cos(ww, idB);                   // row 4
        } else {
            dft8_dual(q, ww, idA, idB);          // rows p, 8-p
        }
        #pragma unroll
        for (int x = 0; x < 8; x++) { idA[x] *= 0.125f; idB[x] *= 0.125f; }
    }

    // ---- Re-pair rows for Haar: rotation shfl (t0:{0,1} t1:{6,7}
    //      t2:{2,3} t3:{4,5}); even threads keep idA, odd keep idB ----
    float ev[8], od[8];
    {
        const int src = b + 8 * ((p + 1) & 3);
        #pragma unroll
        for (int x = 0; x < 8; x++) {
            float snd = hi1 ? idA[x] : idB[x];
            float rcv = __shfl_sync(0xffffffffu, snd, src);
            ev[x] = hi1 ? rcv : idA[x];
            od[x] = hi1 ? idB[x] : rcv;
        }
    }
    const int rl = hi1 ? (7 - p) : p;            // even row of my pair
    const int Rg = 8 * w + rl;                   // strip-local even row

    const int bidx = z / 3;
    const int cch = z - bidx * 3;
    const size_t obase =
        ((size_t)(bidx * 6 + cch) * 512 + (tileY + Rg)) * 512 + tileX + b * 8;

    // ---- I-branch: haar + store ----
    {
        float oa[8], ob[8];
        haar_pair(ev, od, oa, ob);
        float4* q0 = (float4*)(out + obase);
        q0[0] = make_float4(oa[0], oa[1], oa[2], oa[3]);
        q0[1] = make_float4(oa[4], oa[5], oa[6], oa[7]);
        float4* q1 = (float4*)(out + obase + 512);
        q1[0] = make_float4(ob[0], ob[1], ob[2], ob[3]);
        q1[1] = make_float4(ob[4], ob[5], ob[6], ob[7]);
    }

    // ---- R-branch: recompute blur rows rl, rl+1, residual, haar, store ----
    {
        const float4* hp2 = (const float4*)(panel + Rg * 8);
        float rdA[8], rdB[8];
        vblur2(hp2, w0, w1, rdA, rdB);           // g rows rl, rl+1
        #pragma unroll
        for (int x = 0; x < 8; x++) { rdA[x] -= ev[x]; rdB[x] -= od[x]; }
        float oa[8], ob[8];
        haar_pair(rdA, rdB, oa, ob);
        const size_t rbase = obase + (size_t)3 * 512 * 512;
        float4* q0 = (float4*)(out + rbase);
        q0[0] = make_float4(oa[0], oa[1], oa[2], oa[3]);
        q0[1] = make_float4(oa[4], oa[5], oa[6], oa[7]);
        float4* q1 = (float4*)(out + rbase + 512);
        q1[0] = make_float4(ob[0], ob[1], ob[2], ob[3]);
        q1[1] = make_float4(ob[4], ob[5], ob[6], ob[7]);
    }
}

extern "C" void kernel_launch(void* const* d_in, const int* in_sizes, int n_in,
                              void* d_out, int out_size) {
    const float* I = (const float*)d_in[0];
    float* out = (float*)d_out;
    dim3 block(128);
    dim3 grid(8, 16, 96);
    sas_fusedC_kernel<<<grid, block>>>(I, out);
}